// round 13
// baseline (speedup 1.0000x reference)
#include <cuda_runtime.h>
#include <stdint.h>
#include <math.h>

#define BB 256
#define HH 28
#define WW 28

typedef unsigned long long u64;

__device__ __forceinline__ uint32_t f2tf32(float f) {
    uint32_t r;
    asm("cvt.rna.tf32.f32 %0, %1;" : "=r"(r) : "f"(f));
    return r;
}
// D += A(16x8,row) * B(8x8,col), tf32 in, f32 acc
__device__ __forceinline__ void mma_tf32(float& d0, float& d1, float& d2, float& d3,
                                         uint32_t a0, uint32_t a1, uint32_t a2, uint32_t a3,
                                         uint32_t b0, uint32_t b1) {
    asm("mma.sync.aligned.m16n8k8.row.col.f32.tf32.tf32.f32 "
        "{%0,%1,%2,%3}, {%4,%5,%6,%7}, {%8,%9}, {%0,%1,%2,%3};"
        : "+f"(d0), "+f"(d1), "+f"(d2), "+f"(d3)
        : "r"(a0), "r"(a1), "r"(a2), "r"(a3), "r"(b0), "r"(b1));
}

// Scratch (device globals: allocation-free rule). Zero-initialized at module
// load; padded borders of g_h1p/g_h2p are never written -> stay zero.
__device__ float g_h1p[BB*30*30*32];   // conv1 out, NHWC padded, zero border
__device__ float g_offs[BB*28*28*18];  // p_conv offsets, NHWC
__device__ float g_h2p[BB*30*30*32];   // deform out, NHWC padded, zero border
__device__ float g_part[BB*2*64];      // pooled partial sums of relu(conv3)

// ---------------------------------------------------------------------------
// K1: conv1(3->32, pad1) + relu + bn1 -> g_h1p interior  (unchanged)
// ---------------------------------------------------------------------------
__global__ void k1_conv1(const float* __restrict__ x, const float* __restrict__ w1,
                         const float* __restrict__ g1, const float* __restrict__ b1,
                         const float* __restrict__ m1, const float* __restrict__ v1) {
    __shared__ float xs[3*30*30];
    __shared__ float ws[27*32];
    int tid = threadIdx.x;
    int b = blockIdx.x;
    for (int i = tid; i < 2700; i += 256) xs[i] = 0.f;
    for (int i = tid; i < 27*32; i += 256) {
        int t = i >> 5, o = i & 31;
        ws[i] = w1[o*27 + t];
    }
    __syncthreads();
    for (int i = tid; i < 3*28*28; i += 256) {
        int c = i / 784, rem = i % 784;
        int y = rem / 28, xx = rem % 28;
        xs[c*900 + (y+1)*30 + xx+1] = x[b*2352 + i];
    }
    __syncthreads();

    int warp = tid >> 5, lane = tid & 31;
    float inv = g1[lane] * rsqrtf(v1[lane] + 1e-5f);
    float sh  = b1[lane] - m1[lane]*inv;

    for (int y = warp; y < 28; y += 8) {
        float acc[28];
        #pragma unroll
        for (int i = 0; i < 28; i++) acc[i] = 0.f;
        #pragma unroll
        for (int c = 0; c < 3; c++) {
            #pragma unroll
            for (int ky = 0; ky < 3; ky++) {
                const float* arow = &xs[c*900 + (y+ky)*30];
                float w0 = ws[(c*9+ky*3+0)*32 + lane];
                float w1v = ws[(c*9+ky*3+1)*32 + lane];
                float w2 = ws[(c*9+ky*3+2)*32 + lane];
                float a0 = arow[0], a1 = arow[1];
                #pragma unroll
                for (int xx = 0; xx < 28; xx++) {
                    float a2 = arow[xx+2];
                    acc[xx] = fmaf(a0, w0, acc[xx]);
                    acc[xx] = fmaf(a1, w1v, acc[xx]);
                    acc[xx] = fmaf(a2, w2, acc[xx]);
                    a0 = a1; a1 = a2;
                }
            }
        }
        #pragma unroll
        for (int xx = 0; xx < 28; xx++)
            g_h1p[((b*30+y+1)*30 + xx+1)*32 + lane] = fmaxf(acc[xx], 0.f)*inv + sh;
    }
}

// ---------------------------------------------------------------------------
// K2: p_conv(32->18, pad1) + bias -> g_offs, via tf32 mma.  (unchanged, R12)
// ---------------------------------------------------------------------------
__global__ void __launch_bounds__(256, 3)
k2_pconv(const float* __restrict__ wp, const float* __restrict__ bp) {
    extern __shared__ float sm2[];
    uint2* bsh = (uint2*)sm2;            // [((n*4+s)*4+q)*32 + o]
    float* ash = sm2 + 9216;             // [ry][x*36 + c], tf32-rounded
    int tid = threadIdx.x;
    int b = blockIdx.x / 7, strip = blockIdx.x % 7;
    for (int i = tid; i < 4608; i += 256) {
        int o = i & 31, q = (i>>5)&3, s = (i>>7)&3, n = i>>9;
        float lo = 0.f, hi = 0.f;
        if (o < 18) {
            lo = wp[o*288 + (q*8+s)*9 + n];
            hi = wp[o*288 + (q*8+s+4)*9 + n];
        }
        bsh[i] = make_uint2(f2tf32(lo), f2tf32(hi));
    }
    const float4* src = (const float4*)&g_h1p[(b*30 + strip*4)*30*32];
    for (int i = tid; i < 6*30*8; i += 256) {
        int qq = i & 7, px = (i >> 3) % 30, ry = i / 240;
        float4 v = src[i];
        uint4 t4;
        t4.x = f2tf32(v.x); t4.y = f2tf32(v.y); t4.z = f2tf32(v.z); t4.w = f2tf32(v.w);
        *(uint4*)&ash[ry*1080 + px*36 + qq*4] = t4;
    }
    __syncthreads();

    int warp = tid >> 5, lane = tid & 31;
    if (warp >= 7) return;
    int gr = lane >> 2, q = lane & 3;
    int p0 = warp*16 + gr, p1 = p0 + 8;
    int r0 = p0/28, x0 = p0%28, r1 = p1/28, x1 = p1%28;
    float C[3][4];
    #pragma unroll
    for (int t = 0; t < 3; t++)
        #pragma unroll
        for (int j = 0; j < 4; j++) C[t][j] = 0.f;

    #pragma unroll 1
    for (int n = 0; n < 9; n++) {
        int ky = n/3, kx = n%3;
        uint32_t lo0[4], hi0[4], lo1[4], hi1[4];
        const float* a0p = &ash[(r0+ky)*1080 + (x0+kx)*36 + q*8];
        const float* a1p = &ash[(r1+ky)*1080 + (x1+kx)*36 + q*8];
        *(uint4*)lo0 = *(const uint4*)a0p;
        *(uint4*)hi0 = *(const uint4*)(a0p + 4);
        *(uint4*)lo1 = *(const uint4*)a1p;
        *(uint4*)hi1 = *(const uint4*)(a1p + 4);
        #pragma unroll
        for (int s = 0; s < 4; s++) {
            #pragma unroll
            for (int t = 0; t < 3; t++) {
                uint2 bv = bsh[((n*4+s)*4+q)*32 + t*8 + gr];
                mma_tf32(C[t][0], C[t][1], C[t][2], C[t][3],
                         lo0[s], lo1[s], hi0[s], hi1[s], bv.x, bv.y);
            }
        }
    }
    int ybase = strip*4;
    #pragma unroll
    for (int t = 0; t < 3; t++) {
        #pragma unroll
        for (int j = 0; j < 2; j++) {
            int o = t*8 + q*2 + j;
            if (o < 18) {
                float bpv = bp[o];
                g_offs[((b*28 + ybase + r0)*28 + x0)*18 + o] = C[t][j]   + bpv;
                g_offs[((b*28 + ybase + r1)*28 + x1)*18 + o] = C[t][2+j] + bpv;
            }
        }
    }
}

// ---------------------------------------------------------------------------
// K3: fused deformable sample + 9pt conv (32->32) + relu + bn2 -> g_h2p
// R13 change: offsets for the 56-px strip are prefetched (coalesced) into
// smem scratch living in xsh rows 56..63 (the zero-pad region), so phase A's
// per-sample offset reads are 29-cyc broadcast LDS instead of ~600-cyc
// warp-uniform LDG. Rows 56..63 are re-zeroed before phase B.
// smem: bsh uint2[4608] (36864B) + xsh 64*296 floats (75776B) = 112640B
// ---------------------------------------------------------------------------
__global__ void __launch_bounds__(256, 2)
k3_deform(const float* __restrict__ w2, const float* __restrict__ g2,
          const float* __restrict__ b2_, const float* __restrict__ m2,
          const float* __restrict__ v2) {
    extern __shared__ float sm3[];
    uint2* bsh = (uint2*)sm3;            // [((n*4+s)*4+q)*32 + o]
    float* xsh = sm3 + 9216;             // [pl*296 + n*32 + c], tf32 bits
    float* osh = xsh + 56*296;           // scratch: 56*18 offsets (in pad rows)
    int tid = threadIdx.x;
    int b = blockIdx.x / 14, strip = blockIdx.x % 14;
    int y0 = strip*2;
    for (int i = tid; i < 4608; i += 256) {
        int o = i & 31, q = (i>>5)&3, s = (i>>7)&3, n = i>>9;
        bsh[i] = make_uint2(f2tf32(w2[o*288 + (q*8+s)*9 + n]),
                            f2tf32(w2[o*288 + (q*8+s+4)*9 + n]));
    }
    // prefetch the strip's offsets: 56 px x 18 = 1008 contiguous floats
    {
        const float* ob = &g_offs[(b*28 + y0)*28*18];
        for (int i = tid; i < 1008; i += 256) osh[i] = ob[i];
    }
    __syncthreads();

    int warp = tid >> 5, lane = tid & 31;
    const float* img = &g_h1p[b*900*32];

    // Phase A: bilinear sampling (lane = in channel), offsets from smem
    for (int k = 0; k < 7; k++) {
        int pl = warp + k*8;             // 0..55
        int y = y0 + pl/28, x = pl%28;
        const float* offp = &osh[pl*18];
        #pragma unroll
        for (int n = 0; n < 9; n++) {
            float oy = offp[n];
            float ox = offp[9+n];
            float pyr = (float)(y + n/3) + oy;
            float pxr = (float)(x + n%3) + ox;
            float fy = floorf(pyr), fx = floorf(pxr);
            float qy0 = fminf(fmaxf(fy,       0.f), 29.f);
            float qy1 = fminf(fmaxf(fy + 1.f, 0.f), 29.f);
            float qx0 = fminf(fmaxf(fx,       0.f), 29.f);
            float qx1 = fminf(fmaxf(fx + 1.f, 0.f), 29.f);
            float pyc = fminf(fmaxf(pyr, 0.f), 29.f);
            float pxc = fminf(fmaxf(pxr, 0.f), 29.f);
            float glt = (1.f + (qy0 - pyc)) * (1.f + (qx0 - pxc));
            float grb = (1.f - (qy1 - pyc)) * (1.f - (qx1 - pxc));
            float glb = (1.f + (qy0 - pyc)) * (1.f - (qx1 - pxc));
            float grt = (1.f - (qy1 - pyc)) * (1.f + (qx0 - pxc));
            int iy0 = (int)qy0, iy1 = (int)qy1, ix0 = (int)qx0, ix1 = (int)qx1;
            float v00 = img[(iy0*30+ix0)*32 + lane];
            float v11 = img[(iy1*30+ix1)*32 + lane];
            float v01 = img[(iy0*30+ix1)*32 + lane];
            float v10 = img[(iy1*30+ix0)*32 + lane];
            float val = glt*v00 + grb*v11 + glb*v01 + grt*v10;
            xsh[pl*296 + n*32 + lane] = __uint_as_float(f2tf32(val));
        }
    }
    __syncthreads();
    // re-zero pad rows 56..63 (phase B reads them as zero M-padding)
    for (int i = tid; i < 8*296; i += 256)
        xsh[56*296 + i] = 0.f;
    __syncthreads();

    // Phase B: M=64 x K=288 x N=32 via mma
    int mt = warp >> 1;
    int nb = (warp & 1) * 16;
    int gr = lane >> 2, q = lane & 3;
    float C0[4] = {0,0,0,0}, C1[4] = {0,0,0,0};
    const float* abase0 = &xsh[(mt*16 + gr)*296 + q*8];
    const float* abase1 = abase0 + 8*296;
    #pragma unroll 1
    for (int n = 0; n < 9; n++) {
        uint32_t lo0[4], hi0[4], lo1[4], hi1[4];
        *(uint4*)lo0 = *(const uint4*)&abase0[n*32];
        *(uint4*)hi0 = *(const uint4*)&abase0[n*32 + 4];
        *(uint4*)lo1 = *(const uint4*)&abase1[n*32];
        *(uint4*)hi1 = *(const uint4*)&abase1[n*32 + 4];
        #pragma unroll
        for (int s = 0; s < 4; s++) {
            uint2 bv0 = bsh[((n*4+s)*4+q)*32 + nb + gr];
            uint2 bv1 = bsh[((n*4+s)*4+q)*32 + nb + 8 + gr];
            mma_tf32(C0[0], C0[1], C0[2], C0[3],
                     lo0[s], lo1[s], hi0[s], hi1[s], bv0.x, bv0.y);
            mma_tf32(C1[0], C1[1], C1[2], C1[3],
                     lo0[s], lo1[s], hi0[s], hi1[s], bv1.x, bv1.y);
        }
    }
    int pl0 = mt*16 + gr;
    int pl1 = pl0 + 8;
    #pragma unroll
    for (int t = 0; t < 2; t++) {
        const float* Cp = t ? C1 : C0;
        #pragma unroll
        for (int j = 0; j < 2; j++) {
            int o = nb + t*8 + q*2 + j;
            float inv = g2[o] * rsqrtf(v2[o] + 1e-5f);
            float sh  = b2_[o] - m2[o]*inv;
            {
                int y = y0 + pl0/28, x = pl0%28;
                g_h2p[((b*30+y+1)*30 + x+1)*32 + o] = fmaxf(Cp[j], 0.f)*inv + sh;
            }
            if (pl1 < 56) {
                int y = y0 + pl1/28, x = pl1%28;
                g_h2p[((b*30+y+1)*30 + x+1)*32 + o] = fmaxf(Cp[2+j], 0.f)*inv + sh;
            }
        }
    }
}

// ---------------------------------------------------------------------------
// K4: conv3(32->64, pad1) + relu + pooled sum via tf32 mma  (unchanged, R11)
// ---------------------------------------------------------------------------
#define ASTR 36
#define AROW (34*ASTR)
__global__ void __launch_bounds__(256, 2)
k4_conv3(const float* __restrict__ w3) {
    extern __shared__ float ash[];
    int tid = threadIdx.x;
    int b = blockIdx.x >> 1, half = blockIdx.x & 1;
    int warp = tid >> 5, lane = tid & 31;
    int gr = lane >> 2, q = lane & 3;
    int y0p = half * 14;

    for (int i = tid; i < 16*4*ASTR; i += 256) {
        int ry = i / (4*ASTR), r = i % (4*ASTR);
        ash[ry*AROW + 30*ASTR + r] = 0.f;
    }
    const float4* src = (const float4*)&g_h2p[(b*30 + y0p)*30*32];
    for (int i = tid; i < 16*30*8; i += 256) {
        int qq = i & 7, px = (i >> 3) % 30, ry = i / 240;
        float4 v = src[i];
        uint4 t;
        t.x = f2tf32(v.x); t.y = f2tf32(v.y); t.z = f2tf32(v.z); t.w = f2tf32(v.w);
        *(uint4*)&ash[ry*AROW + px*ASTR + qq*4] = t;
    }
    uint32_t breg[9][4][2];
    {
        const float* wrow = &w3[(warp*8 + gr)*288];
        #pragma unroll
        for (int t = 0; t < 9; t++)
            #pragma unroll
            for (int s = 0; s < 4; s++) {
                breg[t][s][0] = f2tf32(wrow[(q*8 + s)*9 + t]);
                breg[t][s][1] = f2tf32(wrow[(q*8 + s + 4)*9 + t]);
            }
    }
    __syncthreads();

    float sp0 = 0.f, sp1 = 0.f;
    #pragma unroll 1
    for (int mt = 0; mt < 28; mt++) {
        int ry = mt >> 1, x0 = (mt & 1) << 4;
        float c0 = 0.f, c1 = 0.f, c2 = 0.f, c3 = 0.f;
        #pragma unroll
        for (int t = 0; t < 9; t++) {
            int ky = t/3, kx = t%3;
            const float* base = &ash[(ry+ky)*AROW + (x0+kx)*ASTR + q*8];
            uint4 lo0 = *(const uint4*)&base[gr*ASTR];
            uint4 hi0 = *(const uint4*)&base[gr*ASTR + 4];
            uint4 lo1 = *(const uint4*)&base[(gr+8)*ASTR];
            uint4 hi1 = *(const uint4*)&base[(gr+8)*ASTR + 4];
            mma_tf32(c0,c1,c2,c3, lo0.x, lo1.x, hi0.x, hi1.x, breg[t][0][0], breg[t][0][1]);
            mma_tf32(c0,c1,c2,c3, lo0.y, lo1.y, hi0.y, hi1.y, breg[t][1][0], breg[t][1][1]);
            mma_tf32(c0,c1,c2,c3, lo0.z, lo1.z, hi0.z, hi1.z, breg[t][2][0], breg[t][2][1]);
            mma_tf32(c0,c1,c2,c3, lo0.w, lo1.w, hi0.w, hi1.w, breg[t][3][0], breg[t][3][1]);
        }
        sp0 += fmaxf(c0, 0.f);
        sp1 += fmaxf(c1, 0.f);
        if (x0 + gr + 8 < 28) {
            sp0 += fmaxf(c2, 0.f);
            sp1 += fmaxf(c3, 0.f);
        }
    }
    #pragma unroll
    for (int off = 4; off < 32; off <<= 1) {
        sp0 += __shfl_xor_sync(0xffffffffu, sp0, off);
        sp1 += __shfl_xor_sync(0xffffffffu, sp1, off);
    }
    if (lane < 4) {
        float* dst = &g_part[(b*2+half)*64 + warp*8 + q*2];
        dst[0] = sp0;
        dst[1] = sp1;
    }
}

// ---------------------------------------------------------------------------
// K5: reduce partials -> mean -> bn3 -> linear(64->10) -> log_softmax
// ---------------------------------------------------------------------------
__global__ void k5_head(const float* __restrict__ g3, const float* __restrict__ b3,
                        const float* __restrict__ m3, const float* __restrict__ v3,
                        const float* __restrict__ wc, const float* __restrict__ bc,
                        float* __restrict__ out) {
    __shared__ float hsh[64];
    __shared__ float lg[10];
    int b = blockIdx.x, tid = threadIdx.x;
    if (tid < 64) {
        float s = g_part[(b*2+0)*64 + tid] + g_part[(b*2+1)*64 + tid];
        s *= (1.f/784.f);
        float inv = g3[tid] * rsqrtf(v3[tid] + 1e-5f);
        hsh[tid] = s * inv + (b3[tid] - m3[tid]*inv);
    }
    __syncthreads();
    if (tid < 10) {
        float acc = bc[tid];
        for (int o = 0; o < 64; o++) acc = fmaf(hsh[o], wc[tid*64 + o], acc);
        lg[tid] = acc;
    }
    __syncthreads();
    if (tid < 10) {
        float mx = -1e30f;
        for (int j = 0; j < 10; j++) mx = fmaxf(mx, lg[j]);
        float se = 0.f;
        for (int j = 0; j < 10; j++) se += expf(lg[j] - mx);
        out[b*10 + tid] = lg[tid] - mx - logf(se);
    }
}

// ---------------------------------------------------------------------------
extern "C" void kernel_launch(void* const* d_in, const int* in_sizes, int n_in,
                              void* d_out, int out_size) {
    const float* x  = (const float*)d_in[0];
    const float* w1 = (const float*)d_in[1];
    const float* g1 = (const float*)d_in[2];
    const float* b1 = (const float*)d_in[3];
    const float* m1 = (const float*)d_in[4];
    const float* v1 = (const float*)d_in[5];
    const float* wp = (const float*)d_in[6];
    const float* bp = (const float*)d_in[7];
    const float* w2 = (const float*)d_in[8];
    const float* g2 = (const float*)d_in[9];
    const float* b2 = (const float*)d_in[10];
    const float* m2 = (const float*)d_in[11];
    const float* v2 = (const float*)d_in[12];
    const float* w3 = (const float*)d_in[13];
    const float* g3 = (const float*)d_in[14];
    const float* b3 = (const float*)d_in[15];
    const float* m3 = (const float*)d_in[16];
    const float* v3 = (const float*)d_in[17];
    const float* wc = (const float*)d_in[18];
    const float* bc = (const float*)d_in[19];

    cudaFuncSetAttribute(k2_pconv,  cudaFuncAttributeMaxDynamicSharedMemorySize, 62784);
    cudaFuncSetAttribute(k3_deform, cudaFuncAttributeMaxDynamicSharedMemorySize, 112640);
    cudaFuncSetAttribute(k4_conv3,  cudaFuncAttributeMaxDynamicSharedMemorySize, 78336);

    k1_conv1<<<BB, 256>>>(x, w1, g1, b1, m1, v1);
    k2_pconv<<<BB*7, 256, 62784>>>(wp, bp);
    k3_deform<<<BB*14, 256, 112640>>>(w2, g2, b2, m2, v2);
    k4_conv3<<<BB*2, 256, 78336>>>(w3);
    k5_head<<<BB, 64>>>(g3, b3, m3, v3, wc, bc, (float*)d_out);
}

// round 14
// speedup vs baseline: 1.1319x; 1.1319x over previous
#include <cuda_runtime.h>
#include <stdint.h>
#include <math.h>

#define BB 256
#define HH 28
#define WW 28

typedef unsigned long long u64;

__device__ __forceinline__ uint32_t f2tf32(float f) {
    uint32_t r;
    asm("cvt.rna.tf32.f32 %0, %1;" : "=r"(r) : "f"(f));
    return r;
}
// D += A(16x8,row) * B(8x8,col), tf32 in, f32 acc
__device__ __forceinline__ void mma_tf32(float& d0, float& d1, float& d2, float& d3,
                                         uint32_t a0, uint32_t a1, uint32_t a2, uint32_t a3,
                                         uint32_t b0, uint32_t b1) {
    asm("mma.sync.aligned.m16n8k8.row.col.f32.tf32.tf32.f32 "
        "{%0,%1,%2,%3}, {%4,%5,%6,%7}, {%8,%9}, {%0,%1,%2,%3};"
        : "+f"(d0), "+f"(d1), "+f"(d2), "+f"(d3)
        : "r"(a0), "r"(a1), "r"(a2), "r"(a3), "r"(b0), "r"(b1));
}

// Scratch (device globals: allocation-free rule). Zero-initialized at module
// load; padded borders of g_h1p/g_h2p are never written -> stay zero.
__device__ float g_h1p[BB*30*30*32];   // conv1 out, NHWC padded, zero border
__device__ float g_offs[BB*28*28*18];  // p_conv offsets, NHWC
__device__ float g_h2p[BB*30*30*32];   // deform out, NHWC padded, zero border
__device__ float g_part[BB*2*64];      // pooled partial sums of relu(conv3)

// ---------------------------------------------------------------------------
// K1: conv1(3->32, pad1) + relu + bn1 -> g_h1p interior  (unchanged)
// ---------------------------------------------------------------------------
__global__ void k1_conv1(const float* __restrict__ x, const float* __restrict__ w1,
                         const float* __restrict__ g1, const float* __restrict__ b1,
                         const float* __restrict__ m1, const float* __restrict__ v1) {
    __shared__ float xs[3*30*30];
    __shared__ float ws[27*32];
    int tid = threadIdx.x;
    int b = blockIdx.x;
    for (int i = tid; i < 2700; i += 256) xs[i] = 0.f;
    for (int i = tid; i < 27*32; i += 256) {
        int t = i >> 5, o = i & 31;
        ws[i] = w1[o*27 + t];
    }
    __syncthreads();
    for (int i = tid; i < 3*28*28; i += 256) {
        int c = i / 784, rem = i % 784;
        int y = rem / 28, xx = rem % 28;
        xs[c*900 + (y+1)*30 + xx+1] = x[b*2352 + i];
    }
    __syncthreads();

    int warp = tid >> 5, lane = tid & 31;
    float inv = g1[lane] * rsqrtf(v1[lane] + 1e-5f);
    float sh  = b1[lane] - m1[lane]*inv;

    for (int y = warp; y < 28; y += 8) {
        float acc[28];
        #pragma unroll
        for (int i = 0; i < 28; i++) acc[i] = 0.f;
        #pragma unroll
        for (int c = 0; c < 3; c++) {
            #pragma unroll
            for (int ky = 0; ky < 3; ky++) {
                const float* arow = &xs[c*900 + (y+ky)*30];
                float w0 = ws[(c*9+ky*3+0)*32 + lane];
                float w1v = ws[(c*9+ky*3+1)*32 + lane];
                float w2 = ws[(c*9+ky*3+2)*32 + lane];
                float a0 = arow[0], a1 = arow[1];
                #pragma unroll
                for (int xx = 0; xx < 28; xx++) {
                    float a2 = arow[xx+2];
                    acc[xx] = fmaf(a0, w0, acc[xx]);
                    acc[xx] = fmaf(a1, w1v, acc[xx]);
                    acc[xx] = fmaf(a2, w2, acc[xx]);
                    a0 = a1; a1 = a2;
                }
            }
        }
        #pragma unroll
        for (int xx = 0; xx < 28; xx++)
            g_h1p[((b*30+y+1)*30 + xx+1)*32 + lane] = fmaxf(acc[xx], 0.f)*inv + sh;
    }
}

// ---------------------------------------------------------------------------
// K2: p_conv(32->18, pad1) + bias -> g_offs, via tf32 mma.  (unchanged, R12)
// ---------------------------------------------------------------------------
__global__ void __launch_bounds__(256, 3)
k2_pconv(const float* __restrict__ wp, const float* __restrict__ bp) {
    extern __shared__ float sm2[];
    uint2* bsh = (uint2*)sm2;            // [((n*4+s)*4+q)*32 + o]
    float* ash = sm2 + 9216;             // [ry][x*36 + c], tf32-rounded
    int tid = threadIdx.x;
    int b = blockIdx.x / 7, strip = blockIdx.x % 7;
    for (int i = tid; i < 4608; i += 256) {
        int o = i & 31, q = (i>>5)&3, s = (i>>7)&3, n = i>>9;
        float lo = 0.f, hi = 0.f;
        if (o < 18) {
            lo = wp[o*288 + (q*8+s)*9 + n];
            hi = wp[o*288 + (q*8+s+4)*9 + n];
        }
        bsh[i] = make_uint2(f2tf32(lo), f2tf32(hi));
    }
    const float4* src = (const float4*)&g_h1p[(b*30 + strip*4)*30*32];
    for (int i = tid; i < 6*30*8; i += 256) {
        int qq = i & 7, px = (i >> 3) % 30, ry = i / 240;
        float4 v = src[i];
        uint4 t4;
        t4.x = f2tf32(v.x); t4.y = f2tf32(v.y); t4.z = f2tf32(v.z); t4.w = f2tf32(v.w);
        *(uint4*)&ash[ry*1080 + px*36 + qq*4] = t4;
    }
    __syncthreads();

    int warp = tid >> 5, lane = tid & 31;
    if (warp >= 7) return;
    int gr = lane >> 2, q = lane & 3;
    int p0 = warp*16 + gr, p1 = p0 + 8;
    int r0 = p0/28, x0 = p0%28, r1 = p1/28, x1 = p1%28;
    float C[3][4];
    #pragma unroll
    for (int t = 0; t < 3; t++)
        #pragma unroll
        for (int j = 0; j < 4; j++) C[t][j] = 0.f;

    #pragma unroll 1
    for (int n = 0; n < 9; n++) {
        int ky = n/3, kx = n%3;
        uint32_t lo0[4], hi0[4], lo1[4], hi1[4];
        const float* a0p = &ash[(r0+ky)*1080 + (x0+kx)*36 + q*8];
        const float* a1p = &ash[(r1+ky)*1080 + (x1+kx)*36 + q*8];
        *(uint4*)lo0 = *(const uint4*)a0p;
        *(uint4*)hi0 = *(const uint4*)(a0p + 4);
        *(uint4*)lo1 = *(const uint4*)a1p;
        *(uint4*)hi1 = *(const uint4*)(a1p + 4);
        #pragma unroll
        for (int s = 0; s < 4; s++) {
            #pragma unroll
            for (int t = 0; t < 3; t++) {
                uint2 bv = bsh[((n*4+s)*4+q)*32 + t*8 + gr];
                mma_tf32(C[t][0], C[t][1], C[t][2], C[t][3],
                         lo0[s], lo1[s], hi0[s], hi1[s], bv.x, bv.y);
            }
        }
    }
    int ybase = strip*4;
    #pragma unroll
    for (int t = 0; t < 3; t++) {
        #pragma unroll
        for (int j = 0; j < 2; j++) {
            int o = t*8 + q*2 + j;
            if (o < 18) {
                float bpv = bp[o];
                g_offs[((b*28 + ybase + r0)*28 + x0)*18 + o] = C[t][j]   + bpv;
                g_offs[((b*28 + ybase + r1)*28 + x1)*18 + o] = C[t][2+j] + bpv;
            }
        }
    }
}

// ---------------------------------------------------------------------------
// K3: fused deformable sample + 9pt conv (32->32) + relu + bn2 -> g_h2p
// R14: exact R12 barrier structure (bsh fill overlaps phase A; ONE barrier).
// Phase A offsets are software-pipelined in registers: iteration k uses
// cur[18] while ov[18] prefetches pixel k+1's offsets (no barriers added).
// smem: bsh uint2[4608] (36864B) + xsh 64*296 floats (75776B) = 112640B
// ---------------------------------------------------------------------------
__global__ void __launch_bounds__(256, 2)
k3_deform(const float* __restrict__ w2, const float* __restrict__ g2,
          const float* __restrict__ b2_, const float* __restrict__ m2,
          const float* __restrict__ v2) {
    extern __shared__ float sm3[];
    uint2* bsh = (uint2*)sm3;            // [((n*4+s)*4+q)*32 + o]
    float* xsh = sm3 + 9216;             // [pl*296 + n*32 + c], tf32 bits
    int tid = threadIdx.x;
    int b = blockIdx.x / 14, strip = blockIdx.x % 14;
    int y0 = strip*2;
    for (int i = tid; i < 4608; i += 256) {
        int o = i & 31, q = (i>>5)&3, s = (i>>7)&3, n = i>>9;
        bsh[i] = make_uint2(f2tf32(w2[o*288 + (q*8+s)*9 + n]),
                            f2tf32(w2[o*288 + (q*8+s+4)*9 + n]));
    }
    for (int i = tid; i < 8*296; i += 256)
        xsh[56*296 + i] = 0.f;

    int warp = tid >> 5, lane = tid & 31;
    const float* img = &g_h1p[b*900*32];

    // Phase A: bilinear sampling (lane = in channel), offsets reg-pipelined
    float ov[18];
    {
        int pl = warp;
        int y = y0 + pl/28, x = pl%28;
        const float* p = &g_offs[((b*28+y)*28+x)*18];
        #pragma unroll
        for (int j = 0; j < 18; j++) ov[j] = p[j];
    }
    for (int k = 0; k < 7; k++) {
        float cur[18];
        #pragma unroll
        for (int j = 0; j < 18; j++) cur[j] = ov[j];
        if (k < 6) {
            int pln = warp + (k+1)*8;
            int yn = y0 + pln/28, xn = pln%28;
            const float* p = &g_offs[((b*28+yn)*28+xn)*18];
            #pragma unroll
            for (int j = 0; j < 18; j++) ov[j] = p[j];
        }
        int pl = warp + k*8;             // 0..55
        int y = y0 + pl/28, x = pl%28;
        #pragma unroll
        for (int n = 0; n < 9; n++) {
            float oy = cur[n];
            float ox = cur[9+n];
            float pyr = (float)(y + n/3) + oy;
            float pxr = (float)(x + n%3) + ox;
            float fy = floorf(pyr), fx = floorf(pxr);
            float qy0 = fminf(fmaxf(fy,       0.f), 29.f);
            float qy1 = fminf(fmaxf(fy + 1.f, 0.f), 29.f);
            float qx0 = fminf(fmaxf(fx,       0.f), 29.f);
            float qx1 = fminf(fmaxf(fx + 1.f, 0.f), 29.f);
            float pyc = fminf(fmaxf(pyr, 0.f), 29.f);
            float pxc = fminf(fmaxf(pxr, 0.f), 29.f);
            float glt = (1.f + (qy0 - pyc)) * (1.f + (qx0 - pxc));
            float grb = (1.f - (qy1 - pyc)) * (1.f - (qx1 - pxc));
            float glb = (1.f + (qy0 - pyc)) * (1.f - (qx1 - pxc));
            float grt = (1.f - (qy1 - pyc)) * (1.f + (qx0 - pxc));
            int iy0 = (int)qy0, iy1 = (int)qy1, ix0 = (int)qx0, ix1 = (int)qx1;
            float v00 = img[(iy0*30+ix0)*32 + lane];
            float v11 = img[(iy1*30+ix1)*32 + lane];
            float v01 = img[(iy0*30+ix1)*32 + lane];
            float v10 = img[(iy1*30+ix0)*32 + lane];
            float val = glt*v00 + grb*v11 + glb*v01 + grt*v10;
            xsh[pl*296 + n*32 + lane] = __uint_as_float(f2tf32(val));
        }
    }
    __syncthreads();

    // Phase B: M=64 x K=288 x N=32 via mma
    int mt = warp >> 1;
    int nb = (warp & 1) * 16;
    int gr = lane >> 2, q = lane & 3;
    float C0[4] = {0,0,0,0}, C1[4] = {0,0,0,0};
    const float* abase0 = &xsh[(mt*16 + gr)*296 + q*8];
    const float* abase1 = abase0 + 8*296;
    #pragma unroll 1
    for (int n = 0; n < 9; n++) {
        uint32_t lo0[4], hi0[4], lo1[4], hi1[4];
        *(uint4*)lo0 = *(const uint4*)&abase0[n*32];
        *(uint4*)hi0 = *(const uint4*)&abase0[n*32 + 4];
        *(uint4*)lo1 = *(const uint4*)&abase1[n*32];
        *(uint4*)hi1 = *(const uint4*)&abase1[n*32 + 4];
        #pragma unroll
        for (int s = 0; s < 4; s++) {
            uint2 bv0 = bsh[((n*4+s)*4+q)*32 + nb + gr];
            uint2 bv1 = bsh[((n*4+s)*4+q)*32 + nb + 8 + gr];
            mma_tf32(C0[0], C0[1], C0[2], C0[3],
                     lo0[s], lo1[s], hi0[s], hi1[s], bv0.x, bv0.y);
            mma_tf32(C1[0], C1[1], C1[2], C1[3],
                     lo0[s], lo1[s], hi0[s], hi1[s], bv1.x, bv1.y);
        }
    }
    int pl0 = mt*16 + gr;
    int pl1 = pl0 + 8;
    #pragma unroll
    for (int t = 0; t < 2; t++) {
        const float* Cp = t ? C1 : C0;
        #pragma unroll
        for (int j = 0; j < 2; j++) {
            int o = nb + t*8 + q*2 + j;
            float inv = g2[o] * rsqrtf(v2[o] + 1e-5f);
            float sh  = b2_[o] - m2[o]*inv;
            {
                int y = y0 + pl0/28, x = pl0%28;
                g_h2p[((b*30+y+1)*30 + x+1)*32 + o] = fmaxf(Cp[j], 0.f)*inv + sh;
            }
            if (pl1 < 56) {
                int y = y0 + pl1/28, x = pl1%28;
                g_h2p[((b*30+y+1)*30 + x+1)*32 + o] = fmaxf(Cp[2+j], 0.f)*inv + sh;
            }
        }
    }
}

// ---------------------------------------------------------------------------
// K4: conv3(32->64, pad1) + relu + pooled sum via tf32 mma  (unchanged, R11)
// ---------------------------------------------------------------------------
#define ASTR 36
#define AROW (34*ASTR)
__global__ void __launch_bounds__(256, 2)
k4_conv3(const float* __restrict__ w3) {
    extern __shared__ float ash[];
    int tid = threadIdx.x;
    int b = blockIdx.x >> 1, half = blockIdx.x & 1;
    int warp = tid >> 5, lane = tid & 31;
    int gr = lane >> 2, q = lane & 3;
    int y0p = half * 14;

    for (int i = tid; i < 16*4*ASTR; i += 256) {
        int ry = i / (4*ASTR), r = i % (4*ASTR);
        ash[ry*AROW + 30*ASTR + r] = 0.f;
    }
    const float4* src = (const float4*)&g_h2p[(b*30 + y0p)*30*32];
    for (int i = tid; i < 16*30*8; i += 256) {
        int qq = i & 7, px = (i >> 3) % 30, ry = i / 240;
        float4 v = src[i];
        uint4 t;
        t.x = f2tf32(v.x); t.y = f2tf32(v.y); t.z = f2tf32(v.z); t.w = f2tf32(v.w);
        *(uint4*)&ash[ry*AROW + px*ASTR + qq*4] = t;
    }
    uint32_t breg[9][4][2];
    {
        const float* wrow = &w3[(warp*8 + gr)*288];
        #pragma unroll
        for (int t = 0; t < 9; t++)
            #pragma unroll
            for (int s = 0; s < 4; s++) {
                breg[t][s][0] = f2tf32(wrow[(q*8 + s)*9 + t]);
                breg[t][s][1] = f2tf32(wrow[(q*8 + s + 4)*9 + t]);
            }
    }
    __syncthreads();

    float sp0 = 0.f, sp1 = 0.f;
    #pragma unroll 1
    for (int mt = 0; mt < 28; mt++) {
        int ry = mt >> 1, x0 = (mt & 1) << 4;
        float c0 = 0.f, c1 = 0.f, c2 = 0.f, c3 = 0.f;
        #pragma unroll
        for (int t = 0; t < 9; t++) {
            int ky = t/3, kx = t%3;
            const float* base = &ash[(ry+ky)*AROW + (x0+kx)*ASTR + q*8];
            uint4 lo0 = *(const uint4*)&base[gr*ASTR];
            uint4 hi0 = *(const uint4*)&base[gr*ASTR + 4];
            uint4 lo1 = *(const uint4*)&base[(gr+8)*ASTR];
            uint4 hi1 = *(const uint4*)&base[(gr+8)*ASTR + 4];
            mma_tf32(c0,c1,c2,c3, lo0.x, lo1.x, hi0.x, hi1.x, breg[t][0][0], breg[t][0][1]);
            mma_tf32(c0,c1,c2,c3, lo0.y, lo1.y, hi0.y, hi1.y, breg[t][1][0], breg[t][1][1]);
            mma_tf32(c0,c1,c2,c3, lo0.z, lo1.z, hi0.z, hi1.z, breg[t][2][0], breg[t][2][1]);
            mma_tf32(c0,c1,c2,c3, lo0.w, lo1.w, hi0.w, hi1.w, breg[t][3][0], breg[t][3][1]);
        }
        sp0 += fmaxf(c0, 0.f);
        sp1 += fmaxf(c1, 0.f);
        if (x0 + gr + 8 < 28) {
            sp0 += fmaxf(c2, 0.f);
            sp1 += fmaxf(c3, 0.f);
        }
    }
    #pragma unroll
    for (int off = 4; off < 32; off <<= 1) {
        sp0 += __shfl_xor_sync(0xffffffffu, sp0, off);
        sp1 += __shfl_xor_sync(0xffffffffu, sp1, off);
    }
    if (lane < 4) {
        float* dst = &g_part[(b*2+half)*64 + warp*8 + q*2];
        dst[0] = sp0;
        dst[1] = sp1;
    }
}

// ---------------------------------------------------------------------------
// K5: reduce partials -> mean -> bn3 -> linear(64->10) -> log_softmax
// ---------------------------------------------------------------------------
__global__ void k5_head(const float* __restrict__ g3, const float* __restrict__ b3,
                        const float* __restrict__ m3, const float* __restrict__ v3,
                        const float* __restrict__ wc, const float* __restrict__ bc,
                        float* __restrict__ out) {
    __shared__ float hsh[64];
    __shared__ float lg[10];
    int b = blockIdx.x, tid = threadIdx.x;
    if (tid < 64) {
        float s = g_part[(b*2+0)*64 + tid] + g_part[(b*2+1)*64 + tid];
        s *= (1.f/784.f);
        float inv = g3[tid] * rsqrtf(v3[tid] + 1e-5f);
        hsh[tid] = s * inv + (b3[tid] - m3[tid]*inv);
    }
    __syncthreads();
    if (tid < 10) {
        float acc = bc[tid];
        for (int o = 0; o < 64; o++) acc = fmaf(hsh[o], wc[tid*64 + o], acc);
        lg[tid] = acc;
    }
    __syncthreads();
    if (tid < 10) {
        float mx = -1e30f;
        for (int j = 0; j < 10; j++) mx = fmaxf(mx, lg[j]);
        float se = 0.f;
        for (int j = 0; j < 10; j++) se += expf(lg[j] - mx);
        out[b*10 + tid] = lg[tid] - mx - logf(se);
    }
}

// ---------------------------------------------------------------------------
extern "C" void kernel_launch(void* const* d_in, const int* in_sizes, int n_in,
                              void* d_out, int out_size) {
    const float* x  = (const float*)d_in[0];
    const float* w1 = (const float*)d_in[1];
    const float* g1 = (const float*)d_in[2];
    const float* b1 = (const float*)d_in[3];
    const float* m1 = (const float*)d_in[4];
    const float* v1 = (const float*)d_in[5];
    const float* wp = (const float*)d_in[6];
    const float* bp = (const float*)d_in[7];
    const float* w2 = (const float*)d_in[8];
    const float* g2 = (const float*)d_in[9];
    const float* b2 = (const float*)d_in[10];
    const float* m2 = (const float*)d_in[11];
    const float* v2 = (const float*)d_in[12];
    const float* w3 = (const float*)d_in[13];
    const float* g3 = (const float*)d_in[14];
    const float* b3 = (const float*)d_in[15];
    const float* m3 = (const float*)d_in[16];
    const float* v3 = (const float*)d_in[17];
    const float* wc = (const float*)d_in[18];
    const float* bc = (const float*)d_in[19];

    cudaFuncSetAttribute(k2_pconv,  cudaFuncAttributeMaxDynamicSharedMemorySize, 62784);
    cudaFuncSetAttribute(k3_deform, cudaFuncAttributeMaxDynamicSharedMemorySize, 112640);
    cudaFuncSetAttribute(k4_conv3,  cudaFuncAttributeMaxDynamicSharedMemorySize, 78336);

    k1_conv1<<<BB, 256>>>(x, w1, g1, b1, m1, v1);
    k2_pconv<<<BB*7, 256, 62784>>>(wp, bp);
    k3_deform<<<BB*14, 256, 112640>>>(w2, g2, b2, m2, v2);
    k4_conv3<<<BB*2, 256, 78336>>>(w3);
    k5_head<<<BB, 64>>>(g3, b3, m3, v3, wc, bc, (float*)d_out);
}

// round 15
// speedup vs baseline: 1.5827x; 1.3983x over previous
#include <cuda_runtime.h>
#include <stdint.h>
#include <math.h>

#define BB 256
#define HH 28
#define WW 28

typedef unsigned long long u64;

__device__ __forceinline__ uint32_t f2tf32(float f) {
    uint32_t r;
    asm("cvt.rna.tf32.f32 %0, %1;" : "=r"(r) : "f"(f));
    return r;
}
// D += A(16x8,row) * B(8x8,col), tf32 in, f32 acc
__device__ __forceinline__ void mma_tf32(float& d0, float& d1, float& d2, float& d3,
                                         uint32_t a0, uint32_t a1, uint32_t a2, uint32_t a3,
                                         uint32_t b0, uint32_t b1) {
    asm("mma.sync.aligned.m16n8k8.row.col.f32.tf32.tf32.f32 "
        "{%0,%1,%2,%3}, {%4,%5,%6,%7}, {%8,%9}, {%0,%1,%2,%3};"
        : "+f"(d0), "+f"(d1), "+f"(d2), "+f"(d3)
        : "r"(a0), "r"(a1), "r"(a2), "r"(a3), "r"(b0), "r"(b1));
}

// Scratch (device globals: allocation-free rule). Zero-initialized at module
// load; padded borders of g_h1p/g_h2p are never written -> stay zero.
__device__ float g_h1p[BB*30*30*32];   // conv1 out, NHWC padded, zero border
__device__ float g_offs[BB*28*28*18];  // p_conv offsets, NHWC
__device__ float g_h2p[BB*30*30*32];   // deform out, NHWC padded, zero border
__device__ float g_part[BB*2*64];      // pooled partial sums of relu(conv3)
// Pre-permuted tf32 weight matrices (packed once by k0_pack):
__device__ uint2    g_b2[4608];        // k2 bsh layout [((n*4+s)*4+q)*32 + o]
__device__ uint2    g_b3[4608];        // k3 bsh layout (same indexing, w2)
__device__ uint32_t g_b4[72*256];      // k4 breg: [((t*4+s)*2+h)*256 + tid]

// ---------------------------------------------------------------------------
// K0: pack permuted tf32 weights once (27648 work items, coalesced writes)
// ---------------------------------------------------------------------------
__global__ void k0_pack(const float* __restrict__ wp, const float* __restrict__ w2,
                        const float* __restrict__ w3) {
    int idx = blockIdx.x*256 + threadIdx.x;
    if (idx < 4608) {
        int i = idx;
        int o = i & 31, q = (i>>5)&3, s = (i>>7)&3, n = i>>9;
        float lo = 0.f, hi = 0.f;
        if (o < 18) {
            lo = wp[o*288 + (q*8+s)*9 + n];
            hi = wp[o*288 + (q*8+s+4)*9 + n];
        }
        g_b2[i] = make_uint2(f2tf32(lo), f2tf32(hi));
    } else if (idx < 9216) {
        int i = idx - 4608;
        int o = i & 31, q = (i>>5)&3, s = (i>>7)&3, n = i>>9;
        g_b3[i] = make_uint2(f2tf32(w2[o*288 + (q*8+s)*9 + n]),
                             f2tf32(w2[o*288 + (q*8+s+4)*9 + n]));
    } else if (idx < 27648) {
        int j = idx - 9216;
        int slot = j >> 8, tid = j & 255;          // slot = (t*4+s)*2+h
        int h = slot & 1, s = (slot >> 1) & 3, t = slot >> 3;
        int warp = tid >> 5, gr = (tid & 31) >> 2, q = tid & 3;
        g_b4[j] = f2tf32(w3[(warp*8 + gr)*288 + (q*8 + s + 4*h)*9 + t]);
    }
}

// ---------------------------------------------------------------------------
// K1: conv1(3->32, pad1) + relu + bn1 -> g_h1p interior  (unchanged)
// ---------------------------------------------------------------------------
__global__ void k1_conv1(const float* __restrict__ x, const float* __restrict__ w1,
                         const float* __restrict__ g1, const float* __restrict__ b1,
                         const float* __restrict__ m1, const float* __restrict__ v1) {
    __shared__ float xs[3*30*30];
    __shared__ float ws[27*32];
    int tid = threadIdx.x;
    int b = blockIdx.x;
    for (int i = tid; i < 2700; i += 256) xs[i] = 0.f;
    for (int i = tid; i < 27*32; i += 256) {
        int t = i >> 5, o = i & 31;
        ws[i] = w1[o*27 + t];
    }
    __syncthreads();
    for (int i = tid; i < 3*28*28; i += 256) {
        int c = i / 784, rem = i % 784;
        int y = rem / 28, xx = rem % 28;
        xs[c*900 + (y+1)*30 + xx+1] = x[b*2352 + i];
    }
    __syncthreads();

    int warp = tid >> 5, lane = tid & 31;
    float inv = g1[lane] * rsqrtf(v1[lane] + 1e-5f);
    float sh  = b1[lane] - m1[lane]*inv;

    for (int y = warp; y < 28; y += 8) {
        float acc[28];
        #pragma unroll
        for (int i = 0; i < 28; i++) acc[i] = 0.f;
        #pragma unroll
        for (int c = 0; c < 3; c++) {
            #pragma unroll
            for (int ky = 0; ky < 3; ky++) {
                const float* arow = &xs[c*900 + (y+ky)*30];
                float w0 = ws[(c*9+ky*3+0)*32 + lane];
                float w1v = ws[(c*9+ky*3+1)*32 + lane];
                float w2 = ws[(c*9+ky*3+2)*32 + lane];
                float a0 = arow[0], a1 = arow[1];
                #pragma unroll
                for (int xx = 0; xx < 28; xx++) {
                    float a2 = arow[xx+2];
                    acc[xx] = fmaf(a0, w0, acc[xx]);
                    acc[xx] = fmaf(a1, w1v, acc[xx]);
                    acc[xx] = fmaf(a2, w2, acc[xx]);
                    a0 = a1; a1 = a2;
                }
            }
        }
        #pragma unroll
        for (int xx = 0; xx < 28; xx++)
            g_h1p[((b*30+y+1)*30 + xx+1)*32 + lane] = fmaxf(acc[xx], 0.f)*inv + sh;
    }
}

// ---------------------------------------------------------------------------
// K2: p_conv(32->18, pad1) + bias -> g_offs, via tf32 mma.
// R15: bsh filled by coalesced copy from g_b2 (32x fewer wavefronts).
// ---------------------------------------------------------------------------
__global__ void __launch_bounds__(256, 3)
k2_pconv(const float* __restrict__ bp) {
    extern __shared__ float sm2[];
    uint2* bsh = (uint2*)sm2;            // [((n*4+s)*4+q)*32 + o]
    float* ash = sm2 + 9216;             // [ry][x*36 + c], tf32-rounded
    int tid = threadIdx.x;
    int b = blockIdx.x / 7, strip = blockIdx.x % 7;
    for (int i = tid; i < 4608; i += 256) bsh[i] = g_b2[i];
    const float4* src = (const float4*)&g_h1p[(b*30 + strip*4)*30*32];
    for (int i = tid; i < 6*30*8; i += 256) {
        int qq = i & 7, px = (i >> 3) % 30, ry = i / 240;
        float4 v = src[i];
        uint4 t4;
        t4.x = f2tf32(v.x); t4.y = f2tf32(v.y); t4.z = f2tf32(v.z); t4.w = f2tf32(v.w);
        *(uint4*)&ash[ry*1080 + px*36 + qq*4] = t4;
    }
    __syncthreads();

    int warp = tid >> 5, lane = tid & 31;
    if (warp >= 7) return;
    int gr = lane >> 2, q = lane & 3;
    int p0 = warp*16 + gr, p1 = p0 + 8;
    int r0 = p0/28, x0 = p0%28, r1 = p1/28, x1 = p1%28;
    float C[3][4];
    #pragma unroll
    for (int t = 0; t < 3; t++)
        #pragma unroll
        for (int j = 0; j < 4; j++) C[t][j] = 0.f;

    #pragma unroll 1
    for (int n = 0; n < 9; n++) {
        int ky = n/3, kx = n%3;
        uint32_t lo0[4], hi0[4], lo1[4], hi1[4];
        const float* a0p = &ash[(r0+ky)*1080 + (x0+kx)*36 + q*8];
        const float* a1p = &ash[(r1+ky)*1080 + (x1+kx)*36 + q*8];
        *(uint4*)lo0 = *(const uint4*)a0p;
        *(uint4*)hi0 = *(const uint4*)(a0p + 4);
        *(uint4*)lo1 = *(const uint4*)a1p;
        *(uint4*)hi1 = *(const uint4*)(a1p + 4);
        #pragma unroll
        for (int s = 0; s < 4; s++) {
            #pragma unroll
            for (int t = 0; t < 3; t++) {
                uint2 bv = bsh[((n*4+s)*4+q)*32 + t*8 + gr];
                mma_tf32(C[t][0], C[t][1], C[t][2], C[t][3],
                         lo0[s], lo1[s], hi0[s], hi1[s], bv.x, bv.y);
            }
        }
    }
    int ybase = strip*4;
    #pragma unroll
    for (int t = 0; t < 3; t++) {
        #pragma unroll
        for (int j = 0; j < 2; j++) {
            int o = t*8 + q*2 + j;
            if (o < 18) {
                float bpv = bp[o];
                g_offs[((b*28 + ybase + r0)*28 + x0)*18 + o] = C[t][j]   + bpv;
                g_offs[((b*28 + ybase + r1)*28 + x1)*18 + o] = C[t][2+j] + bpv;
            }
        }
    }
}

// ---------------------------------------------------------------------------
// K3: fused deformable sample + 9pt conv (32->32) + relu + bn2 -> g_h2p
// R15: R12 structure (ONE barrier, fills overlap phase A); bsh from g_b3
// via coalesced copy. Phase A offsets read directly (R12 form).
// smem: bsh uint2[4608] (36864B) + xsh 64*296 floats (75776B) = 112640B
// ---------------------------------------------------------------------------
__global__ void __launch_bounds__(256, 2)
k3_deform(const float* __restrict__ g2, const float* __restrict__ b2_,
          const float* __restrict__ m2, const float* __restrict__ v2) {
    extern __shared__ float sm3[];
    uint2* bsh = (uint2*)sm3;            // [((n*4+s)*4+q)*32 + o]
    float* xsh = sm3 + 9216;             // [pl*296 + n*32 + c], tf32 bits
    int tid = threadIdx.x;
    int b = blockIdx.x / 14, strip = blockIdx.x % 14;
    int y0 = strip*2;
    for (int i = tid; i < 4608; i += 256) bsh[i] = g_b3[i];
    for (int i = tid; i < 8*296; i += 256)
        xsh[56*296 + i] = 0.f;

    int warp = tid >> 5, lane = tid & 31;
    const float* img = &g_h1p[b*900*32];

    // Phase A: bilinear sampling (lane = in channel)
    for (int k = 0; k < 7; k++) {
        int pl = warp + k*8;             // 0..55
        int y = y0 + pl/28, x = pl%28;
        const float* offp = &g_offs[((b*28+y)*28+x)*18];
        #pragma unroll
        for (int n = 0; n < 9; n++) {
            float oy = offp[n];
            float ox = offp[9+n];
            float pyr = (float)(y + n/3) + oy;
            float pxr = (float)(x + n%3) + ox;
            float fy = floorf(pyr), fx = floorf(pxr);
            float qy0 = fminf(fmaxf(fy,       0.f), 29.f);
            float qy1 = fminf(fmaxf(fy + 1.f, 0.f), 29.f);
            float qx0 = fminf(fmaxf(fx,       0.f), 29.f);
            float qx1 = fminf(fmaxf(fx + 1.f, 0.f), 29.f);
            float pyc = fminf(fmaxf(pyr, 0.f), 29.f);
            float pxc = fminf(fmaxf(pxr, 0.f), 29.f);
            float glt = (1.f + (qy0 - pyc)) * (1.f + (qx0 - pxc));
            float grb = (1.f - (qy1 - pyc)) * (1.f - (qx1 - pxc));
            float glb = (1.f + (qy0 - pyc)) * (1.f - (qx1 - pxc));
            float grt = (1.f - (qy1 - pyc)) * (1.f + (qx0 - pxc));
            int iy0 = (int)qy0, iy1 = (int)qy1, ix0 = (int)qx0, ix1 = (int)qx1;
            float v00 = img[(iy0*30+ix0)*32 + lane];
            float v11 = img[(iy1*30+ix1)*32 + lane];
            float v01 = img[(iy0*30+ix1)*32 + lane];
            float v10 = img[(iy1*30+ix0)*32 + lane];
            float val = glt*v00 + grb*v11 + glb*v01 + grt*v10;
            xsh[pl*296 + n*32 + lane] = __uint_as_float(f2tf32(val));
        }
    }
    __syncthreads();

    // Phase B: M=64 x K=288 x N=32 via mma
    int mt = warp >> 1;
    int nb = (warp & 1) * 16;
    int gr = lane >> 2, q = lane & 3;
    float C0[4] = {0,0,0,0}, C1[4] = {0,0,0,0};
    const float* abase0 = &xsh[(mt*16 + gr)*296 + q*8];
    const float* abase1 = abase0 + 8*296;
    #pragma unroll 1
    for (int n = 0; n < 9; n++) {
        uint32_t lo0[4], hi0[4], lo1[4], hi1[4];
        *(uint4*)lo0 = *(const uint4*)&abase0[n*32];
        *(uint4*)hi0 = *(const uint4*)&abase0[n*32 + 4];
        *(uint4*)lo1 = *(const uint4*)&abase1[n*32];
        *(uint4*)hi1 = *(const uint4*)&abase1[n*32 + 4];
        #pragma unroll
        for (int s = 0; s < 4; s++) {
            uint2 bv0 = bsh[((n*4+s)*4+q)*32 + nb + gr];
            uint2 bv1 = bsh[((n*4+s)*4+q)*32 + nb + 8 + gr];
            mma_tf32(C0[0], C0[1], C0[2], C0[3],
                     lo0[s], lo1[s], hi0[s], hi1[s], bv0.x, bv0.y);
            mma_tf32(C1[0], C1[1], C1[2], C1[3],
                     lo0[s], lo1[s], hi0[s], hi1[s], bv1.x, bv1.y);
        }
    }
    int pl0 = mt*16 + gr;
    int pl1 = pl0 + 8;
    #pragma unroll
    for (int t = 0; t < 2; t++) {
        const float* Cp = t ? C1 : C0;
        #pragma unroll
        for (int j = 0; j < 2; j++) {
            int o = nb + t*8 + q*2 + j;
            float inv = g2[o] * rsqrtf(v2[o] + 1e-5f);
            float sh  = b2_[o] - m2[o]*inv;
            {
                int y = y0 + pl0/28, x = pl0%28;
                g_h2p[((b*30+y+1)*30 + x+1)*32 + o] = fmaxf(Cp[j], 0.f)*inv + sh;
            }
            if (pl1 < 56) {
                int y = y0 + pl1/28, x = pl1%28;
                g_h2p[((b*30+y+1)*30 + x+1)*32 + o] = fmaxf(Cp[2+j], 0.f)*inv + sh;
            }
        }
    }
}

// ---------------------------------------------------------------------------
// K4: conv3(32->64, pad1) + relu + pooled sum via tf32 mma
// R15: breg loaded coalesced from g_b4 (prep-packed), rest unchanged.
// ---------------------------------------------------------------------------
#define ASTR 36
#define AROW (34*ASTR)
__global__ void __launch_bounds__(256, 2)
k4_conv3() {
    extern __shared__ float ash[];
    int tid = threadIdx.x;
    int b = blockIdx.x >> 1, half = blockIdx.x & 1;
    int warp = tid >> 5, lane = tid & 31;
    int gr = lane >> 2, q = lane & 3;
    int y0p = half * 14;

    for (int i = tid; i < 16*4*ASTR; i += 256) {
        int ry = i / (4*ASTR), r = i % (4*ASTR);
        ash[ry*AROW + 30*ASTR + r] = 0.f;
    }
    const float4* src = (const float4*)&g_h2p[(b*30 + y0p)*30*32];
    for (int i = tid; i < 16*30*8; i += 256) {
        int qq = i & 7, px = (i >> 3) % 30, ry = i / 240;
        float4 v = src[i];
        uint4 t;
        t.x = f2tf32(v.x); t.y = f2tf32(v.y); t.z = f2tf32(v.z); t.w = f2tf32(v.w);
        *(uint4*)&ash[ry*AROW + px*ASTR + qq*4] = t;
    }
    uint32_t breg[9][4][2];
    #pragma unroll
    for (int t = 0; t < 9; t++)
        #pragma unroll
        for (int s = 0; s < 4; s++) {
            breg[t][s][0] = g_b4[((t*4+s)*2+0)*256 + tid];
            breg[t][s][1] = g_b4[((t*4+s)*2+1)*256 + tid];
        }
    __syncthreads();

    float sp0 = 0.f, sp1 = 0.f;
    #pragma unroll 1
    for (int mt = 0; mt < 28; mt++) {
        int ry = mt >> 1, x0 = (mt & 1) << 4;
        float c0 = 0.f, c1 = 0.f, c2 = 0.f, c3 = 0.f;
        #pragma unroll
        for (int t = 0; t < 9; t++) {
            int ky = t/3, kx = t%3;
            const float* base = &ash[(ry+ky)*AROW + (x0+kx)*ASTR + q*8];
            uint4 lo0 = *(const uint4*)&base[gr*ASTR];
            uint4 hi0 = *(const uint4*)&base[gr*ASTR + 4];
            uint4 lo1 = *(const uint4*)&base[(gr+8)*ASTR];
            uint4 hi1 = *(const uint4*)&base[(gr+8)*ASTR + 4];
            mma_tf32(c0,c1,c2,c3, lo0.x, lo1.x, hi0.x, hi1.x, breg[t][0][0], breg[t][0][1]);
            mma_tf32(c0,c1,c2,c3, lo0.y, lo1.y, hi0.y, hi1.y, breg[t][1][0], breg[t][1][1]);
            mma_tf32(c0,c1,c2,c3, lo0.z, lo1.z, hi0.z, hi1.z, breg[t][2][0], breg[t][2][1]);
            mma_tf32(c0,c1,c2,c3, lo0.w, lo1.w, hi0.w, hi1.w, breg[t][3][0], breg[t][3][1]);
        }
        sp0 += fmaxf(c0, 0.f);
        sp1 += fmaxf(c1, 0.f);
        if (x0 + gr + 8 < 28) {
            sp0 += fmaxf(c2, 0.f);
            sp1 += fmaxf(c3, 0.f);
        }
    }
    #pragma unroll
    for (int off = 4; off < 32; off <<= 1) {
        sp0 += __shfl_xor_sync(0xffffffffu, sp0, off);
        sp1 += __shfl_xor_sync(0xffffffffu, sp1, off);
    }
    if (lane < 4) {
        float* dst = &g_part[(b*2+half)*64 + warp*8 + q*2];
        dst[0] = sp0;
        dst[1] = sp1;
    }
}

// ---------------------------------------------------------------------------
// K5: reduce partials -> mean -> bn3 -> linear(64->10) -> log_softmax
// ---------------------------------------------------------------------------
__global__ void k5_head(const float* __restrict__ g3, const float* __restrict__ b3,
                        const float* __restrict__ m3, const float* __restrict__ v3,
                        const float* __restrict__ wc, const float* __restrict__ bc,
                        float* __restrict__ out) {
    __shared__ float hsh[64];
    __shared__ float lg[10];
    int b = blockIdx.x, tid = threadIdx.x;
    if (tid < 64) {
        float s = g_part[(b*2+0)*64 + tid] + g_part[(b*2+1)*64 + tid];
        s *= (1.f/784.f);
        float inv = g3[tid] * rsqrtf(v3[tid] + 1e-5f);
        hsh[tid] = s * inv + (b3[tid] - m3[tid]*inv);
    }
    __syncthreads();
    if (tid < 10) {
        float acc = bc[tid];
        for (int o = 0; o < 64; o++) acc = fmaf(hsh[o], wc[tid*64 + o], acc);
        lg[tid] = acc;
    }
    __syncthreads();
    if (tid < 10) {
        float mx = -1e30f;
        for (int j = 0; j < 10; j++) mx = fmaxf(mx, lg[j]);
        float se = 0.f;
        for (int j = 0; j < 10; j++) se += expf(lg[j] - mx);
        out[b*10 + tid] = lg[tid] - mx - logf(se);
    }
}

// ---------------------------------------------------------------------------
extern "C" void kernel_launch(void* const* d_in, const int* in_sizes, int n_in,
                              void* d_out, int out_size) {
    const float* x  = (const float*)d_in[0];
    const float* w1 = (const float*)d_in[1];
    const float* g1 = (const float*)d_in[2];
    const float* b1 = (const float*)d_in[3];
    const float* m1 = (const float*)d_in[4];
    const float* v1 = (const float*)d_in[5];
    const float* wp = (const float*)d_in[6];
    const float* bp = (const float*)d_in[7];
    const float* w2 = (const float*)d_in[8];
    const float* g2 = (const float*)d_in[9];
    const float* b2 = (const float*)d_in[10];
    const float* m2 = (const float*)d_in[11];
    const float* v2 = (const float*)d_in[12];
    const float* w3 = (const float*)d_in[13];
    const float* g3 = (const float*)d_in[14];
    const float* b3 = (const float*)d_in[15];
    const float* m3 = (const float*)d_in[16];
    const float* v3 = (const float*)d_in[17];
    const float* wc = (const float*)d_in[18];
    const float* bc = (const float*)d_in[19];

    cudaFuncSetAttribute(k2_pconv,  cudaFuncAttributeMaxDynamicSharedMemorySize, 62784);
    cudaFuncSetAttribute(k3_deform, cudaFuncAttributeMaxDynamicSharedMemorySize, 112640);
    cudaFuncSetAttribute(k4_conv3,  cudaFuncAttributeMaxDynamicSharedMemorySize, 78336);

    k0_pack<<<108, 256>>>(wp, w2, w3);
    k1_conv1<<<BB, 256>>>(x, w1, g1, b1, m1, v1);
    k2_pconv<<<BB*7, 256, 62784>>>(bp);
    k3_deform<<<BB*14, 256, 112640>>>(g2, b2, m2, v2);
    k4_conv3<<<BB*2, 256, 78336>>>();
    k5_head<<<BB, 64>>>(g3, b3, m3, v3, wc, bc, (float*)d_out);
}